// round 14
// baseline (speedup 1.0000x reference)
#include <cuda_runtime.h>
#include <cstdint>

#define NN 8192      // nodes
#define HD 128       // hidden dim
#define EE 16384     // edges
#define EDF 16       // edge feature dim
#define MH 64        // mlp hidden
#define KC2 8320     // (MH+1)*HD columns of U (65th k-block carries b2)
#define G3 384       // 3*HD gate columns

// ---- scratch (static __device__, allocation-guard safe) ----
__device__ float g_hid[EE * MH];            // relu(ef@W1+b1)            (4MB)
__device__ float g_m[NN * HD];              // scatter accumulator       (4MB)
__device__ float g_gi[NN * G3];             // m @ W_ih^T                (12.6MB)
__device__ float g_gh[NN * G3];             // h @ W_hh^T                (12.6MB)
__device__ float g_U[(size_t)NN * KC2];     // per-node transformed      (~273MB)

// ===========================================================================
// helpers
// ===========================================================================
__device__ __forceinline__ float to_tf32(float x) {
    float y;
    asm("cvt.rna.tf32.f32 %0, %1;" : "=f"(y) : "f"(x));
    return y;
}
__device__ __forceinline__ void mma_tf32(float& c0, float& c1, float& c2, float& c3,
                                         uint32_t a0, uint32_t a1, uint32_t a2, uint32_t a3,
                                         uint32_t b0, uint32_t b1) {
    asm volatile(
        "mma.sync.aligned.m16n8k8.row.col.f32.tf32.tf32.f32 "
        "{%0,%1,%2,%3}, {%4,%5,%6,%7}, {%8,%9}, {%0,%1,%2,%3};"
        : "+f"(c0), "+f"(c1), "+f"(c2), "+f"(c3)
        : "r"(a0), "r"(a1), "r"(a2), "r"(a3), "r"(b0), "r"(b1));
}

// ===========================================================================
// hid_kernel: g_hid[e,k] = relu(b1[k] + sum_t ef[e,t]*W1[t,k]); also zeroes g_m
// ===========================================================================
__global__ void hid_kernel(const float* __restrict__ ef, const float* __restrict__ W1,
                           const float* __restrict__ b1) {
    __shared__ float W1s[EDF * MH];
    __shared__ float b1s[MH];
    int tid = threadIdx.x;
    for (int i2 = tid; i2 < EDF * MH; i2 += blockDim.x) W1s[i2] = W1[i2];
    if (tid < MH) b1s[tid] = b1[tid];
    __syncthreads();
    int idx = blockIdx.x * blockDim.x + tid;    // e*64 + k
    int e = idx >> 6, k = idx & 63;
    float acc = b1s[k];
    const float* efe = ef + e * EDF;
    #pragma unroll
    for (int t = 0; t < EDF; t++) acc += efe[t] * W1s[t * MH + k];
    g_hid[idx] = fmaxf(acc, 0.0f);
    g_m[idx] = 0.0f;
}

// ===========================================================================
// 128x128x128 tf32 MMA tile (R10 fragment layout, bitwise-identical math),
// extended to MULTI-TILE: A stays resident in smem; CTA loops over NT B tiles
// with a cross-tile software pipeline (B LDGs one tile ahead; scatter into the
// half-buffer the current compute is not reading).
//   A_f[mb(8)][kc(16)][lane(32)][q(4)]   (64 KB)
//   B_f[nb(16)][kc(16)][lane(32)][qb(2)] (64 KB)
// 512 threads = 16 warps (4M x 4N), warp tile 32x32.
// ===========================================================================
#define U_SMEM_BYTES (2 * 16384 * 4)   // 128 KB

__device__ __forceinline__ void scatA(float* __restrict__ A_f, int row, int c4, float4 v) {
    int kc = c4 >> 1, qp = c4 & 1;
    int qa = qp * 2 + ((row >> 3) & 1);
    int abase = (((row >> 4) * 16 + kc) * 32) * 4;
    int swz = kc & 7;
    float av[4] = {v.x, v.y, v.z, v.w};
    #pragma unroll
    for (int dk = 0; dk < 4; dk++) {
        int L = ((row & 7) * 4 + dk) ^ swz;
        A_f[abase + L * 4 + qa] = to_tf32(av[dk]);
    }
}
__device__ __forceinline__ void scatB(float* __restrict__ B_f, int row, int c4, float4 v) {
    int kc = c4 >> 1, qp = c4 & 1;
    int bbase = (((row >> 3) * 16 + kc) * 32) * 2;
    int swz = kc & 7;
    float bv[4] = {v.x, v.y, v.z, v.w};
    #pragma unroll
    for (int dk = 0; dk < 4; dk++) {
        int L = ((row & 7) * 4 + dk) ^ swz;
        B_f[bbase + L * 2 + qp] = to_tf32(bv[dk]);
    }
}

__device__ __forceinline__ void compute_half(const float* __restrict__ A_f,
                                             const float* __restrict__ B_f,
                                             int lane, int warp_mb, int warp_nb,
                                             int klo, float acc[2][4][4]) {
    #pragma unroll
    for (int kk = 0; kk < 8; kk++) {
        int kc = klo + kk;
        int Lp = lane ^ (kc & 7);
        float4 af[2];
        float2 bf[4];
        #pragma unroll
        for (int mf = 0; mf < 2; mf++)
            af[mf] = *reinterpret_cast<const float4*>(
                &A_f[(((warp_mb + mf) * 16 + kc) * 32 + Lp) * 4]);
        #pragma unroll
        for (int nf = 0; nf < 4; nf++)
            bf[nf] = *reinterpret_cast<const float2*>(
                &B_f[(((warp_nb + nf) * 16 + kc) * 32 + Lp) * 2]);
        #pragma unroll
        for (int mf = 0; mf < 2; mf++)
            #pragma unroll
            for (int nf = 0; nf < 4; nf++)
                mma_tf32(acc[mf][nf][0], acc[mf][nf][1], acc[mf][nf][2], acc[mf][nf][3],
                         __float_as_uint(af[mf].x), __float_as_uint(af[mf].y),
                         __float_as_uint(af[mf].z), __float_as_uint(af[mf].w),
                         __float_as_uint(bf[nf].x), __float_as_uint(bf[nf].y));
    }
}

// B tile pointer for logical tile index idx: idx<64 -> Bbase + idx*16384,
// else Bover (u_mma's bias block). gate_mma never reaches the override.
__device__ __forceinline__ const float4* tileB(const float* Bbase, const float* Bover,
                                               int idx) {
    const float* p = (idx < 64) ? (Bbase + (size_t)idx * 16384) : Bover;
    return reinterpret_cast<const float4*>(p);
}

// C[128, NT*128] = A[128,128] @ B_t[128,128]^T for NT consecutive tiles.
__device__ __forceinline__ void gemm_tiles(const float4* __restrict__ A4,
                                           const float* __restrict__ Bbase, int idx0,
                                           const float* __restrict__ Bover,
                                           float* __restrict__ Cbase, size_t ldc, int NT,
                                           float* A_f, float* B_f) {
    int tid = threadIdx.x;

    // ---- scatter A (full K=128) once; A stays resident ----
    #pragma unroll
    for (int p = 0; p < 8; p++) {
        int idx4 = tid + p * 512;           // 0..4095
        float4 v = A4[idx4];
        scatA(A_f, idx4 >> 5, idx4 & 31, v);
    }

    int lane = tid & 31, wid = tid >> 5;
    int warp_mb = (wid & 3) * 2;
    int warp_nb = (wid >> 2) * 4;
    int g = lane >> 2, tg = lane & 3;
    int warp_m = (wid & 3) * 32;
    int warp_n = (wid >> 2) * 32;

    float4 vb0[4], vb1[4];
    // prologue: tile 0 half0 -> smem, half1 -> regs
    {
        const float4* B4 = tileB(Bbase, Bover, idx0);
        #pragma unroll
        for (int p = 0; p < 4; p++) {
            int i4 = tid + p * 512;
            vb0[p] = B4[(i4 >> 4) * 32 + (i4 & 15)];
        }
        #pragma unroll
        for (int p = 0; p < 4; p++) {
            int i4 = tid + p * 512;
            scatB(B_f, i4 >> 4, i4 & 15, vb0[p]);
        }
        #pragma unroll
        for (int p = 0; p < 4; p++) {
            int i4 = tid + p * 512;
            vb1[p] = B4[(i4 >> 4) * 32 + (i4 & 15) + 16];
        }
    }
    __syncthreads();

    for (int t = 0; t < NT; t++) {
        float acc[2][4][4];
        #pragma unroll
        for (int mf = 0; mf < 2; mf++)
            #pragma unroll
            for (int nf = 0; nf < 4; nf++)
                #pragma unroll
                for (int q = 0; q < 4; q++) acc[mf][nf][q] = 0.0f;

        compute_half(A_f, B_f, lane, warp_mb, warp_nb, 0, acc);

        // scatter half1 of current tile (kc8-15; prior readers done at last sync)
        #pragma unroll
        for (int p = 0; p < 4; p++) {
            int i4 = tid + p * 512;
            scatB(B_f, i4 >> 4, (i4 & 15) + 16, vb1[p]);
        }
        if (t + 1 < NT) {                   // LDG next tile half0
            const float4* Bn = tileB(Bbase, Bover, idx0 + t + 1);
            #pragma unroll
            for (int p = 0; p < 4; p++) {
                int i4 = tid + p * 512;
                vb0[p] = Bn[(i4 >> 4) * 32 + (i4 & 15)];
            }
        }
        __syncthreads();

        compute_half(A_f, B_f, lane, warp_mb, warp_nb, 8, acc);

        if (t + 1 < NT) {
            // scatter next tile half0 (kc0-7; current readers only touch kc8-15)
            #pragma unroll
            for (int p = 0; p < 4; p++) {
                int i4 = tid + p * 512;
                scatB(B_f, i4 >> 4, i4 & 15, vb0[p]);
            }
            const float4* Bn = tileB(Bbase, Bover, idx0 + t + 1);
            #pragma unroll
            for (int p = 0; p < 4; p++) {
                int i4 = tid + p * 512;
                vb1[p] = Bn[(i4 >> 4) * 32 + (i4 & 15) + 16];
            }
        }

        // ---- epilogue for tile t ----
        float* Cb = Cbase + (size_t)t * 128;
        #pragma unroll
        for (int mf = 0; mf < 2; mf++) {
            int row = warp_m + mf * 16 + g;
            #pragma unroll
            for (int nf = 0; nf < 4; nf++) {
                int col = warp_n + nf * 8 + 2 * tg;
                float* d0 = Cb + (size_t)row * ldc + col;
                *reinterpret_cast<float2*>(d0) =
                    make_float2(acc[mf][nf][0], acc[mf][nf][1]);
                *reinterpret_cast<float2*>(d0 + (size_t)8 * ldc) =
                    make_float2(acc[mf][nf][2], acc[mf][nf][3]);
            }
        }
        __syncthreads();                    // next-tile half0 visible; kc8-15 reads done
    }
}

// ===========================================================================
// u_mma_kernel: U[n][col] = sum_j h[n][j] * B[col][j]  (col = k*128+i)
//   grid (64, 13): CTA (x,gy) computes node block x, colblocks gy*5..gy*5+4
//   (65 colblocks total; #64 = b2 bias block). A (h tile) resident across tiles.
// ===========================================================================
__global__ __launch_bounds__(512) void u_mma_kernel(
        const float* __restrict__ hin, const float* __restrict__ W2,
        const float* __restrict__ b2) {
    extern __shared__ float smem[];
    int n0 = blockIdx.x * 128;
    int y0 = blockIdx.y * 5;
    gemm_tiles(reinterpret_cast<const float4*>(hin + (size_t)n0 * HD),
               W2, y0, b2,
               g_U + (size_t)n0 * KC2 + (size_t)y0 * 128, KC2, 5,
               smem, smem + 16384);
}

// ===========================================================================
// gate_mma_kernel: C[n,i] = sum_j A[n,j]*W[i,j]  (tf32 mma)
//   grid (64, 2): y=0: A=g_m, W=W_ih -> g_gi ; y=1: A=h, W=W_hh -> g_gh
//   3 colblocks of 128 per CTA, A resident.
// ===========================================================================
__global__ __launch_bounds__(512) void gate_mma_kernel(
        const float* __restrict__ hin,
        const float* __restrict__ W_ih, const float* __restrict__ W_hh) {
    extern __shared__ float smem[];
    int n0 = blockIdx.x * 128;
    const float* A = blockIdx.y ? hin : (const float*)g_m;
    const float* W = blockIdx.y ? W_hh : W_ih;
    float* C = blockIdx.y ? g_gh : g_gi;
    gemm_tiles(reinterpret_cast<const float4*>(A + (size_t)n0 * HD),
               W, 0, nullptr,
               C + (size_t)n0 * G3, G3, 3,
               smem, smem + 16384);
}

// ===========================================================================
// msg_kernel: warp per edge. Lane l owns float4 columns [4l,4l+4).
//   messages[e] = U[src][64-block] (bias, w=1) + sum_k hid[e,k]*U[src][k-block]
//   Predicated LDG.128 skips relu-zeroed k (uniform predicate per warp).
// ===========================================================================
#define MEB 8   // edges per block (8 warps, 256 threads)
__global__ __launch_bounds__(256) void msg_kernel(const int* __restrict__ edge_index) {
    __shared__ float hid_s[MEB][MH];
    __shared__ int s_src[MEB], s_tgt[MEB];
    int tid = threadIdx.x;
    int e0 = blockIdx.x * MEB;
    if (tid < MEB) {
        s_src[tid] = edge_index[e0 + tid];
        s_tgt[tid] = edge_index[EE + e0 + tid];
    }
    for (int idx = tid; idx < MEB * MH; idx += 256)
        hid_s[idx >> 6][idx & 63] = g_hid[e0 * MH + idx];
    __syncthreads();

    int we = tid >> 5, lane = tid & 31;
    const float4* Ur = reinterpret_cast<const float4*>(
        g_U + (size_t)s_src[we] * KC2) + lane;

    float4 a0 = Ur[MH * 32];                // bias block, weight 1
    float4 a1 = make_float4(0.f, 0.f, 0.f, 0.f);
    #pragma unroll 8
    for (int k = 0; k < MH; k += 2) {
        float w0 = hid_s[we][k], w1 = hid_s[we][k + 1];
        if (w0 != 0.f) {
            float4 v = Ur[k * 32];
            a0.x += w0 * v.x; a0.y += w0 * v.y; a0.z += w0 * v.z; a0.w += w0 * v.w;
        }
        if (w1 != 0.f) {
            float4 v = Ur[(k + 1) * 32];
            a1.x += w1 * v.x; a1.y += w1 * v.y; a1.z += w1 * v.z; a1.w += w1 * v.w;
        }
    }
    float* mdst = g_m + s_tgt[we] * HD + lane * 4;
    atomicAdd(mdst + 0, a0.x + a1.x);
    atomicAdd(mdst + 1, a0.y + a1.y);
    atomicAdd(mdst + 2, a0.z + a1.z);
    atomicAdd(mdst + 3, a0.w + a1.w);
}

// ===========================================================================
// gru_elem: fused gate nonlinearity + blend (coalesced, memory-bound)
// ===========================================================================
__global__ void gru_elem(const float* __restrict__ hin,
                         const float* __restrict__ b_ih, const float* __restrict__ b_hh,
                         float* __restrict__ out) {
    int idx = blockIdx.x * blockDim.x + threadIdx.x;    // n*128 + i
    int n = idx >> 7, i = idx & 127;
    const float* gi = g_gi + n * G3;
    const float* gh = g_gh + n * G3;
    float r = 1.0f / (1.0f + expf(-(gi[i] + b_ih[i] + gh[i] + b_hh[i])));
    float z = 1.0f / (1.0f + expf(-(gi[HD + i] + b_ih[HD + i] + gh[HD + i] + b_hh[HD + i])));
    float ng = tanhf(gi[2 * HD + i] + b_ih[2 * HD + i]
                     + r * (gh[2 * HD + i] + b_hh[2 * HD + i]));
    float hv = hin[idx];
    out[idx] = (1.0f - z) * ng + z * hv;
}

// ===========================================================================
// metadata order: h, edge_index, edge_features, W1, b1, W2, b2,
//                 W_ih, W_hh, b_ih, b_hh ; output float32 [N, H]
// ===========================================================================
extern "C" void kernel_launch(void* const* d_in, const int* in_sizes, int n_in,
                              void* d_out, int out_size) {
    const float* h_ptr      = (const float*)d_in[0];
    const int*   edge_index = (const int*)  d_in[1];
    const float* ef         = (const float*)d_in[2];
    const float* W1         = (const float*)d_in[3];
    const float* b1         = (const float*)d_in[4];
    const float* W2         = (const float*)d_in[5];
    const float* b2         = (const float*)d_in[6];
    const float* W_ih       = (const float*)d_in[7];
    const float* W_hh       = (const float*)d_in[8];
    const float* b_ih       = (const float*)d_in[9];
    const float* b_hh       = (const float*)d_in[10];
    float* out = (float*)d_out;

    cudaFuncSetAttribute(u_mma_kernel, cudaFuncAttributeMaxDynamicSharedMemorySize,
                         U_SMEM_BYTES);
    cudaFuncSetAttribute(gate_mma_kernel, cudaFuncAttributeMaxDynamicSharedMemorySize,
                         U_SMEM_BYTES);

    hid_kernel<<<(EE * MH) / 256, 256>>>(ef, W1, b1);
    u_mma_kernel<<<dim3(NN / 128, 13), 512, U_SMEM_BYTES>>>(h_ptr, W2, b2);
    msg_kernel<<<EE / MEB, 256>>>(edge_index);
    gate_mma_kernel<<<dim3(NN / 128, 2), 512, U_SMEM_BYTES>>>(h_ptr, W_ih, W_hh);
    gru_elem<<<(NN * HD) / 256, 256>>>(h_ptr, b_ih, b_hh, out);
}

// round 15
// speedup vs baseline: 1.3175x; 1.3175x over previous
#include <cuda_runtime.h>
#include <cstdint>

#define NN 8192      // nodes
#define HD 128       // hidden dim
#define EE 16384     // edges
#define EDF 16       // edge feature dim
#define MH 64        // mlp hidden
#define KC2 8320     // (MH+1)*HD columns of U (65th k-block carries b2)
#define G3 384       // 3*HD gate columns

// ---- scratch (static __device__, allocation-guard safe) ----
__device__ float g_hid[EE * MH];            // relu(ef@W1+b1)            (4MB)
__device__ float g_m[NN * HD];              // scatter accumulator       (4MB)
__device__ float g_gi[NN * G3];             // m @ W_ih^T                (12.6MB)
__device__ float g_gh[NN * G3];             // h @ W_hh^T                (12.6MB)
__device__ float g_U[(size_t)NN * KC2];     // per-node transformed      (~273MB)

// ===========================================================================
// helpers
// ===========================================================================
__device__ __forceinline__ float to_tf32(float x) {
    float y;
    asm("cvt.rna.tf32.f32 %0, %1;" : "=f"(y) : "f"(x));
    return y;
}
__device__ __forceinline__ void mma_tf32(float& c0, float& c1, float& c2, float& c3,
                                         uint32_t a0, uint32_t a1, uint32_t a2, uint32_t a3,
                                         uint32_t b0, uint32_t b1) {
    asm volatile(
        "mma.sync.aligned.m16n8k8.row.col.f32.tf32.tf32.f32 "
        "{%0,%1,%2,%3}, {%4,%5,%6,%7}, {%8,%9}, {%0,%1,%2,%3};"
        : "+f"(c0), "+f"(c1), "+f"(c2), "+f"(c3)
        : "r"(a0), "r"(a1), "r"(a2), "r"(a3), "r"(b0), "r"(b1));
}

// ===========================================================================
// hid_kernel: g_hid[e,k] = relu(b1[k] + sum_t ef[e,t]*W1[t,k]); also zeroes g_m
// ===========================================================================
__global__ void hid_kernel(const float* __restrict__ ef, const float* __restrict__ W1,
                           const float* __restrict__ b1) {
    __shared__ float W1s[EDF * MH];
    __shared__ float b1s[MH];
    int tid = threadIdx.x;
    for (int i2 = tid; i2 < EDF * MH; i2 += blockDim.x) W1s[i2] = W1[i2];
    if (tid < MH) b1s[tid] = b1[tid];
    __syncthreads();
    int idx = blockIdx.x * blockDim.x + tid;    // e*64 + k
    int e = idx >> 6, k = idx & 63;
    float acc = b1s[k];
    const float* efe = ef + e * EDF;
    #pragma unroll
    for (int t = 0; t < EDF; t++) acc += efe[t] * W1s[t * MH + k];
    g_hid[idx] = fmaxf(acc, 0.0f);
    g_m[idx] = 0.0f;
}

// ===========================================================================
// R10 128x128x128 tf32 MMA tile (fragment-ready swizzled smem layout):
//   A_f[mb(8)][kc(16)][lane(32)][q(4)]  : q = {(g,tg),(g+8,tg),(g,tg+4),(g+8,tg+4)}
//   B_f[nb(16)][kc(16)][lane(32)][qb(2)]: qb = {(g,tg),(g,tg+4)}
//   lane slot XOR-swizzled by (kc&7); mainloop reads conflict-free LDS.128/64.
// 2-stage K pipeline: LDG half1 issued before compute half0.
// 512 threads, 128 KB dynamic smem.
// ===========================================================================
#define U_SMEM_BYTES (2 * 16384 * 4)   // 128 KB

__device__ __forceinline__ void scatter_frag(float* __restrict__ A_f,
                                             float* __restrict__ B_f,
                                             int row, int c4, float4 va, float4 vb) {
    int kc = c4 >> 1;
    int qp = c4 & 1;
    int r = row & 15;
    int qa = qp * 2 + (r >> 3);
    int mb = row >> 4, nb = row >> 3;
    int swz = kc & 7;
    int abase = ((mb * 16 + kc) * 32) * 4;
    int bbase = ((nb * 16 + kc) * 32) * 2;
    float av[4] = {va.x, va.y, va.z, va.w};
    float bv[4] = {vb.x, vb.y, vb.z, vb.w};
    #pragma unroll
    for (int dk = 0; dk < 4; dk++) {
        int L = ((row & 7) * 4 + dk) ^ swz;
        A_f[abase + L * 4 + qa] = to_tf32(av[dk]);
        B_f[bbase + L * 2 + qp] = to_tf32(bv[dk]);
    }
}

__device__ __forceinline__ void compute_half(const float* __restrict__ A_f,
                                             const float* __restrict__ B_f,
                                             int lane, int warp_mb, int warp_nb,
                                             int klo, float acc[2][4][4]) {
    #pragma unroll
    for (int kk = 0; kk < 8; kk++) {
        int kc = klo + kk;
        int Lp = lane ^ (kc & 7);
        float4 af[2];
        float2 bf[4];
        #pragma unroll
        for (int mf = 0; mf < 2; mf++)
            af[mf] = *reinterpret_cast<const float4*>(
                &A_f[(((warp_mb + mf) * 16 + kc) * 32 + Lp) * 4]);
        #pragma unroll
        for (int nf = 0; nf < 4; nf++)
            bf[nf] = *reinterpret_cast<const float2*>(
                &B_f[(((warp_nb + nf) * 16 + kc) * 32 + Lp) * 2]);
        #pragma unroll
        for (int mf = 0; mf < 2; mf++)
            #pragma unroll
            for (int nf = 0; nf < 4; nf++)
                mma_tf32(acc[mf][nf][0], acc[mf][nf][1], acc[mf][nf][2], acc[mf][nf][3],
                         __float_as_uint(af[mf].x), __float_as_uint(af[mf].y),
                         __float_as_uint(af[mf].z), __float_as_uint(af[mf].w),
                         __float_as_uint(bf[nf].x), __float_as_uint(bf[nf].y));
    }
}

// Full tile: C[128,128] (at Cbase, leading dim ldc) = A[128,128] @ B[128,128]^T
__device__ __forceinline__ void gemm128x128(const float4* __restrict__ A4,
                                            const float4* __restrict__ B4,
                                            float* __restrict__ Cbase, size_t ldc,
                                            float* A_f, float* B_f) {
    int tid = threadIdx.x;

    float4 va[4], vb[4];
    #pragma unroll
    for (int p = 0; p < 4; p++) {
        int t = tid + p * 512;
        va[p] = A4[(t >> 4) * 32 + (t & 15)];
        vb[p] = B4[(t >> 4) * 32 + (t & 15)];
    }
    #pragma unroll
    for (int p = 0; p < 4; p++) {
        int t = tid + p * 512;
        scatter_frag(A_f, B_f, t >> 4, t & 15, va[p], vb[p]);
    }
    __syncthreads();

    // issue global loads for half 1 (latency hidden under compute half 0)
    #pragma unroll
    for (int p = 0; p < 4; p++) {
        int t = tid + p * 512;
        va[p] = A4[(t >> 4) * 32 + (t & 15) + 16];
        vb[p] = B4[(t >> 4) * 32 + (t & 15) + 16];
    }

    int lane = tid & 31, wid = tid >> 5;
    int warp_mb = (wid & 3) * 2;
    int warp_nb = (wid >> 2) * 4;

    float acc[2][4][4];
    #pragma unroll
    for (int mf = 0; mf < 2; mf++)
        #pragma unroll
        for (int nf = 0; nf < 4; nf++)
            #pragma unroll
            for (int q = 0; q < 4; q++) acc[mf][nf][q] = 0.0f;

    compute_half(A_f, B_f, lane, warp_mb, warp_nb, 0, acc);

    #pragma unroll
    for (int p = 0; p < 4; p++) {
        int t = tid + p * 512;
        scatter_frag(A_f, B_f, t >> 4, (t & 15) + 16, va[p], vb[p]);
    }
    __syncthreads();

    compute_half(A_f, B_f, lane, warp_mb, warp_nb, 8, acc);

    int g = lane >> 2, tg = lane & 3;
    int warp_m = (wid & 3) * 32;
    int warp_n = (wid >> 2) * 32;
    #pragma unroll
    for (int mf = 0; mf < 2; mf++) {
        int row = warp_m + mf * 16 + g;
        #pragma unroll
        for (int nf = 0; nf < 4; nf++) {
            int col = warp_n + nf * 8 + 2 * tg;
            float* d0 = Cbase + (size_t)row * ldc + col;
            *reinterpret_cast<float2*>(d0) =
                make_float2(acc[mf][nf][0], acc[mf][nf][1]);
            *reinterpret_cast<float2*>(d0 + (size_t)8 * ldc) =
                make_float2(acc[mf][nf][2], acc[mf][nf][3]);
        }
    }
}

// ===========================================================================
// u_mma_kernel: U[n][col] = sum_j h[n][j] * B[col][j]  (col = k*128+i)
// ===========================================================================
__global__ __launch_bounds__(512) void u_mma_kernel(
        const float* __restrict__ hin, const float* __restrict__ W2,
        const float* __restrict__ b2) {
    extern __shared__ float smem[];
    int n0blk = blockIdx.x * 128;
    int colbase = blockIdx.y * 128;
    const float4* A4 = reinterpret_cast<const float4*>(hin + (size_t)n0blk * HD);
    const float*  Bsrc = (blockIdx.y < 64) ? (W2 + (size_t)blockIdx.y * 16384) : b2;
    gemm128x128(A4, reinterpret_cast<const float4*>(Bsrc),
                g_U + (size_t)n0blk * KC2 + colbase, KC2,
                smem, smem + 16384);
}

// ===========================================================================
// gate_mma_kernel: C[n,i] = sum_j A[n,j]*W[i,j]  (tf32 mma)
//   z=0: A=g_m, W=W_ih -> g_gi ; z=1: A=h, W=W_hh -> g_gh
// ===========================================================================
__global__ __launch_bounds__(512) void gate_mma_kernel(
        const float* __restrict__ hin,
        const float* __restrict__ W_ih, const float* __restrict__ W_hh) {
    extern __shared__ float smem[];
    int n0 = blockIdx.x * 128;
    int colbase = blockIdx.y * 128;         // 0 / 128 / 256
    const float* A = blockIdx.z ? hin : (const float*)g_m;
    const float* W = blockIdx.z ? W_hh : W_ih;
    float* C = blockIdx.z ? g_gh : g_gi;
    gemm128x128(reinterpret_cast<const float4*>(A + (size_t)n0 * HD),
                reinterpret_cast<const float4*>(W + (size_t)colbase * HD),
                C + (size_t)n0 * G3 + colbase, G3,
                smem, smem + 16384);
}

// ===========================================================================
// msg_kernel v4: warp per edge; warp-ballot COMPACTION of nonzero hid k's,
// then a dense loop of 4 independent unguarded LDG.128 per iteration (MLP>=4).
//   messages[e] = U[src][64-block] (bias, w=1) + sum_{k: hid!=0} hid[e,k]*U[src][k-block]
// ===========================================================================
#define MEB 8   // edges per block (8 warps, 256 threads)
__global__ __launch_bounds__(256) void msg_kernel(const int* __restrict__ edge_index) {
    __shared__ float hid_s[MEB][MH];
    __shared__ unsigned char ck_s[MEB][MH];     // compacted nonzero k indices
    __shared__ int s_src[MEB], s_tgt[MEB];
    int tid = threadIdx.x;
    int e0 = blockIdx.x * MEB;
    if (tid < MEB) {
        s_src[tid] = edge_index[e0 + tid];
        s_tgt[tid] = edge_index[EE + e0 + tid];
    }
    for (int idx = tid; idx < MEB * MH; idx += 256)
        hid_s[idx >> 6][idx & 63] = g_hid[e0 * MH + idx];
    __syncthreads();

    int we = tid >> 5, lane = tid & 31;

    // ---- warp-ballot compaction (k = lane and k = lane+32) ----
    float w0 = hid_s[we][lane];
    float w1 = hid_s[we][lane + 32];
    unsigned b0 = __ballot_sync(0xFFFFFFFFu, w0 != 0.f);
    unsigned b1 = __ballot_sync(0xFFFFFFFFu, w1 != 0.f);
    unsigned below = (1u << lane) - 1u;
    if (w0 != 0.f) ck_s[we][__popc(b0 & below)] = (unsigned char)lane;
    if (w1 != 0.f) ck_s[we][__popc(b0) + __popc(b1 & below)] = (unsigned char)(lane + 32);
    int cnt = __popc(b0) + __popc(b1);
    __syncwarp();

    const float4* Ur = reinterpret_cast<const float4*>(
        g_U + (size_t)s_src[we] * KC2) + lane;

    float4 a0 = Ur[MH * 32];                // bias block, weight 1
    float4 a1 = make_float4(0.f, 0.f, 0.f, 0.f);
    float4 a2 = make_float4(0.f, 0.f, 0.f, 0.f);
    float4 a3 = make_float4(0.f, 0.f, 0.f, 0.f);

    int i = 0;
    for (; i + 4 <= cnt; i += 4) {
        int k0 = ck_s[we][i + 0], k1 = ck_s[we][i + 1];
        int k2 = ck_s[we][i + 2], k3 = ck_s[we][i + 3];
        float4 v0 = Ur[k0 * 32];            // 4 independent LDG.128
        float4 v1 = Ur[k1 * 32];
        float4 v2 = Ur[k2 * 32];
        float4 v3 = Ur[k3 * 32];
        float c0 = hid_s[we][k0], c1 = hid_s[we][k1];
        float c2 = hid_s[we][k2], c3 = hid_s[we][k3];
        a0.x += c0 * v0.x; a0.y += c0 * v0.y; a0.z += c0 * v0.z; a0.w += c0 * v0.w;
        a1.x += c1 * v1.x; a1.y += c1 * v1.y; a1.z += c1 * v1.z; a1.w += c1 * v1.w;
        a2.x += c2 * v2.x; a2.y += c2 * v2.y; a2.z += c2 * v2.z; a2.w += c2 * v2.w;
        a3.x += c3 * v3.x; a3.y += c3 * v3.y; a3.z += c3 * v3.z; a3.w += c3 * v3.w;
    }
    for (; i < cnt; i++) {
        int k = ck_s[we][i];
        float4 v = Ur[k * 32];
        float c = hid_s[we][k];
        a0.x += c * v.x; a0.y += c * v.y; a0.z += c * v.z; a0.w += c * v.w;
    }

    float* mdst = g_m + s_tgt[we] * HD + lane * 4;
    atomicAdd(mdst + 0, (a0.x + a1.x) + (a2.x + a3.x));
    atomicAdd(mdst + 1, (a0.y + a1.y) + (a2.y + a3.y));
    atomicAdd(mdst + 2, (a0.z + a1.z) + (a2.z + a3.z));
    atomicAdd(mdst + 3, (a0.w + a1.w) + (a2.w + a3.w));
}

// ===========================================================================
// gru_elem: fused gate nonlinearity + blend (coalesced, memory-bound)
// ===========================================================================
__global__ void gru_elem(const float* __restrict__ hin,
                         const float* __restrict__ b_ih, const float* __restrict__ b_hh,
                         float* __restrict__ out) {
    int idx = blockIdx.x * blockDim.x + threadIdx.x;    // n*128 + i
    int n = idx >> 7, i = idx & 127;
    const float* gi = g_gi + n * G3;
    const float* gh = g_gh + n * G3;
    float r = 1.0f / (1.0f + expf(-(gi[i] + b_ih[i] + gh[i] + b_hh[i])));
    float z = 1.0f / (1.0f + expf(-(gi[HD + i] + b_ih[HD + i] + gh[HD + i] + b_hh[HD + i])));
    float ng = tanhf(gi[2 * HD + i] + b_ih[2 * HD + i]
                     + r * (gh[2 * HD + i] + b_hh[2 * HD + i]));
    float hv = hin[idx];
    out[idx] = (1.0f - z) * ng + z * hv;
}

// ===========================================================================
// metadata order: h, edge_index, edge_features, W1, b1, W2, b2,
//                 W_ih, W_hh, b_ih, b_hh ; output float32 [N, H]
// ===========================================================================
extern "C" void kernel_launch(void* const* d_in, const int* in_sizes, int n_in,
                              void* d_out, int out_size) {
    const float* h_ptr      = (const float*)d_in[0];
    const int*   edge_index = (const int*)  d_in[1];
    const float* ef         = (const float*)d_in[2];
    const float* W1         = (const float*)d_in[3];
    const float* b1         = (const float*)d_in[4];
    const float* W2         = (const float*)d_in[5];
    const float* b2         = (const float*)d_in[6];
    const float* W_ih       = (const float*)d_in[7];
    const float* W_hh       = (const float*)d_in[8];
    const float* b_ih       = (const float*)d_in[9];
    const float* b_hh       = (const float*)d_in[10];
    float* out = (float*)d_out;

    cudaFuncSetAttribute(u_mma_kernel, cudaFuncAttributeMaxDynamicSharedMemorySize,
                         U_SMEM_BYTES);
    cudaFuncSetAttribute(gate_mma_kernel, cudaFuncAttributeMaxDynamicSharedMemorySize,
                         U_SMEM_BYTES);

    hid_kernel<<<(EE * MH) / 256, 256>>>(ef, W1, b1);
    u_mma_kernel<<<dim3(NN / 128, KC2 / 128), 512, U_SMEM_BYTES>>>(h_ptr, W2, b2);
    msg_kernel<<<EE / MEB, 256>>>(edge_index);
    gate_mma_kernel<<<dim3(NN / 128, 3, 2), 512, U_SMEM_BYTES>>>(h_ptr, W_ih, W_hh);
    gru_elem<<<(NN * HD) / 256, 256>>>(h_ptr, b_ih, b_hh, out);
}

// round 17
// speedup vs baseline: 1.6627x; 1.2619x over previous
#include <cuda_runtime.h>
#include <cuda_fp16.h>
#include <cstdint>

#define NN 8192      // nodes
#define HD 128       // hidden dim
#define EE 16384     // edges
#define EDF 16       // edge feature dim
#define MH 64        // mlp hidden
#define KC2 8320     // (MH+1)*HD columns of U (65th k-block carries b2)
#define G3 384       // 3*HD gate columns

// ---- scratch (static __device__, allocation-guard safe) ----
__device__ float g_hid[EE * MH];            // relu(ef@W1+b1)            (4MB)
__device__ float g_m[NN * HD];              // scatter accumulator       (4MB)
__device__ float g_gi[NN * G3];             // m @ W_ih^T                (12.6MB)
__device__ float g_gh[NN * G3];             // h @ W_hh^T                (12.6MB)
__device__ float g_U[(size_t)NN * KC2];     // per-node transformed      (~273MB)

// ===========================================================================
// helpers
// ===========================================================================
__device__ __forceinline__ void mma_f16(float& c0, float& c1, float& c2, float& c3,
                                        uint32_t a0, uint32_t a1, uint32_t a2, uint32_t a3,
                                        uint32_t b0, uint32_t b1) {
    asm volatile(
        "mma.sync.aligned.m16n8k16.row.col.f32.f16.f16.f32 "
        "{%0,%1,%2,%3}, {%4,%5,%6,%7}, {%8,%9}, {%0,%1,%2,%3};"
        : "+f"(c0), "+f"(c1), "+f"(c2), "+f"(c3)
        : "r"(a0), "r"(a1), "r"(a2), "r"(a3), "r"(b0), "r"(b1));
}
__device__ __forceinline__ uint32_t pack_h2(float x, float y) {
    __half2 h = __floats2half2_rn(x, y);
    return *reinterpret_cast<uint32_t*>(&h);
}

// ===========================================================================
// hid_kernel: g_hid[e,k] = relu(b1[k] + sum_t ef[e,t]*W1[t,k]); also zeroes g_m
// ===========================================================================
__global__ void hid_kernel(const float* __restrict__ ef, const float* __restrict__ W1,
                           const float* __restrict__ b1) {
    __shared__ float W1s[EDF * MH];
    __shared__ float b1s[MH];
    int tid = threadIdx.x;
    for (int i2 = tid; i2 < EDF * MH; i2 += blockDim.x) W1s[i2] = W1[i2];
    if (tid < MH) b1s[tid] = b1[tid];
    __syncthreads();
    int idx = blockIdx.x * blockDim.x + tid;    // e*64 + k
    int e = idx >> 6, k = idx & 63;
    float acc = b1s[k];
    const float* efe = ef + e * EDF;
    #pragma unroll
    for (int t = 0; t < EDF; t++) acc += efe[t] * W1s[t * MH + k];
    g_hid[idx] = fmaxf(acc, 0.0f);
    g_m[idx] = 0.0f;
}

// ===========================================================================
// 128x128x128 fp16 MMA tile (m16n8k16, fp32 accum). Fragment-ready smem:
//   A_h[mb(8)][kc(8)][slot(32)][q(4)]  uint32=half2
//     q = {(row g, k 2tg..), (g+8, 2tg..), (g, 2tg+8..), (g+8, 2tg+8..)}
//   B_h[nb(16)][kc(8)][slot(32)][qb(2)] : qb = k-half
//   slot L = (g*4+tg) ^ kc  -> stores <=2-way; reads conflict-free LDS.128/64.
// 2-half K pipeline (k 0..63 / 64..127); 512 threads = 16 warps (4M x 4N).
// fp16 mantissa (11 bits) == tf32 mantissa -> same rounding budget as tf32.
// ===========================================================================
#define U_SMEM_BYTES (2 * 8192 * 4)     // 64 KB (A_h 32K + B_h 32K)

__device__ __forceinline__ void scatA_h(uint32_t* __restrict__ A_h,
                                        int row, int c4, float4 v) {
    int kc = c4 >> 2;                   // global k-chunk 0..7
    int khalf = (c4 & 3) >> 1;
    int tg0 = (c4 & 1) * 2;
    int q = khalf * 2 + ((row >> 3) & 1);
    int mb = row >> 4, g = row & 7;
    int base = (mb * 8 + kc) * 32;
    int L0 = (g * 4 + tg0) ^ kc;
    int L1 = (g * 4 + tg0 + 1) ^ kc;
    A_h[(base + L0) * 4 + q] = pack_h2(v.x, v.y);
    A_h[(base + L1) * 4 + q] = pack_h2(v.z, v.w);
}
__device__ __forceinline__ void scatB_h(uint32_t* __restrict__ B_h,
                                        int row, int c4, float4 v) {
    int kc = c4 >> 2;
    int khalf = (c4 & 3) >> 1;
    int tg0 = (c4 & 1) * 2;
    int nb = row >> 3, g = row & 7;
    int base = (nb * 8 + kc) * 32;
    int L0 = (g * 4 + tg0) ^ kc;
    int L1 = (g * 4 + tg0 + 1) ^ kc;
    B_h[(base + L0) * 2 + khalf] = pack_h2(v.x, v.y);
    B_h[(base + L1) * 2 + khalf] = pack_h2(v.z, v.w);
}

__device__ __forceinline__ void compute_half(const uint32_t* __restrict__ A_h,
                                             const uint32_t* __restrict__ B_h,
                                             int lane, int warp_mb, int warp_nb,
                                             int klo, float acc[2][4][4]) {
    #pragma unroll
    for (int kk = 0; kk < 4; kk++) {
        int kc = klo + kk;
        int Lp = lane ^ kc;
        uint4 af[2];
        uint2 bf[4];
        #pragma unroll
        for (int mf = 0; mf < 2; mf++)
            af[mf] = *reinterpret_cast<const uint4*>(
                &A_h[(((warp_mb + mf) * 8 + kc) * 32 + Lp) * 4]);
        #pragma unroll
        for (int nf = 0; nf < 4; nf++)
            bf[nf] = *reinterpret_cast<const uint2*>(
                &B_h[(((warp_nb + nf) * 8 + kc) * 32 + Lp) * 2]);
        #pragma unroll
        for (int mf = 0; mf < 2; mf++)
            #pragma unroll
            for (int nf = 0; nf < 4; nf++)
                mma_f16(acc[mf][nf][0], acc[mf][nf][1], acc[mf][nf][2], acc[mf][nf][3],
                        af[mf].x, af[mf].y, af[mf].z, af[mf].w,
                        bf[nf].x, bf[nf].y);
    }
}

// Full tile: C[128,128] (at Cbase, leading dim ldc) = A[128,128] @ B[128,128]^T
__device__ __forceinline__ void gemm128x128(const float4* __restrict__ A4,
                                            const float4* __restrict__ B4,
                                            float* __restrict__ Cbase, size_t ldc,
                                            uint32_t* A_h, uint32_t* B_h) {
    int tid = threadIdx.x;

    float4 va[4], vb[4];
    // ---- load + scatter half 0 (c4 0..15, k 0..63) ----
    #pragma unroll
    for (int p = 0; p < 4; p++) {
        int t = tid + p * 512;
        va[p] = A4[(t >> 4) * 32 + (t & 15)];
        vb[p] = B4[(t >> 4) * 32 + (t & 15)];
    }
    #pragma unroll
    for (int p = 0; p < 4; p++) {
        int t = tid + p * 512;
        scatA_h(A_h, t >> 4, t & 15, va[p]);
        scatB_h(B_h, t >> 4, t & 15, vb[p]);
    }
    __syncthreads();

    // issue global loads for half 1 (latency hidden under compute half 0)
    #pragma unroll
    for (int p = 0; p < 4; p++) {
        int t = tid + p * 512;
        va[p] = A4[(t >> 4) * 32 + (t & 15) + 16];
        vb[p] = B4[(t >> 4) * 32 + (t & 15) + 16];
    }

    int lane = tid & 31, wid = tid >> 5;
    int warp_mb = (wid & 3) * 2;
    int warp_nb = (wid >> 2) * 4;

    float acc[2][4][4];
    #pragma unroll
    for (int mf = 0; mf < 2; mf++)
        #pragma unroll
        for (int nf = 0; nf < 4; nf++)
            #pragma unroll
            for (int q = 0; q < 4; q++) acc[mf][nf][q] = 0.0f;

    compute_half(A_h, B_h, lane, warp_mb, warp_nb, 0, acc);

    #pragma unroll
    for (int p = 0; p < 4; p++) {
        int t = tid + p * 512;
        scatA_h(A_h, t >> 4, (t & 15) + 16, va[p]);
        scatB_h(B_h, t >> 4, (t & 15) + 16, vb[p]);
    }
    __syncthreads();

    compute_half(A_h, B_h, lane, warp_mb, warp_nb, 4, acc);

    int g = lane >> 2, tg = lane & 3;
    int warp_m = (wid & 3) * 32;
    int warp_n = (wid >> 2) * 32;
    #pragma unroll
    for (int mf = 0; mf < 2; mf++) {
        int row = warp_m + mf * 16 + g;
        #pragma unroll
        for (int nf = 0; nf < 4; nf++) {
            int col = warp_n + nf * 8 + 2 * tg;
            float* d0 = Cbase + (size_t)row * ldc + col;
            *reinterpret_cast<float2*>(d0) =
                make_float2(acc[mf][nf][0], acc[mf][nf][1]);
            *reinterpret_cast<float2*>(d0 + (size_t)8 * ldc) =
                make_float2(acc[mf][nf][2], acc[mf][nf][3]);
        }
    }
}

// ===========================================================================
// u_mma_kernel: U[n][col] = sum_j h[n][j] * B[col][j]  (col = k*128+i)
// ===========================================================================
__global__ __launch_bounds__(512) void u_mma_kernel(
        const float* __restrict__ hin, const float* __restrict__ W2,
        const float* __restrict__ b2) {
    extern __shared__ uint32_t smem_u[];
    int n0blk = blockIdx.x * 128;
    int colbase = blockIdx.y * 128;
    const float4* A4 = reinterpret_cast<const float4*>(hin + (size_t)n0blk * HD);
    const float*  Bsrc = (blockIdx.y < 64) ? (W2 + (size_t)blockIdx.y * 16384) : b2;
    gemm128x128(A4, reinterpret_cast<const float4*>(Bsrc),
                g_U + (size_t)n0blk * KC2 + colbase, KC2,
                smem_u, smem_u + 8192);
}

// ===========================================================================
// gate_mma_kernel: C[n,i] = sum_j A[n,j]*W[i,j]
//   z=0: A=g_m, W=W_ih -> g_gi ; z=1: A=h, W=W_hh -> g_gh
// ===========================================================================
__global__ __launch_bounds__(512) void gate_mma_kernel(
        const float* __restrict__ hin,
        const float* __restrict__ W_ih, const float* __restrict__ W_hh) {
    extern __shared__ uint32_t smem_u[];
    int n0 = blockIdx.x * 128;
    int colbase = blockIdx.y * 128;         // 0 / 128 / 256
    const float* A = blockIdx.z ? hin : (const float*)g_m;
    const float* W = blockIdx.z ? W_hh : W_ih;
    float* C = blockIdx.z ? g_gh : g_gi;
    gemm128x128(reinterpret_cast<const float4*>(A + (size_t)n0 * HD),
                reinterpret_cast<const float4*>(W + (size_t)colbase * HD),
                C + (size_t)n0 * G3 + colbase, G3,
                smem_u, smem_u + 8192);
}

// ===========================================================================
// msg_kernel (R10 version): warp per edge, lane l owns float4 cols [4l,4l+4).
//   messages[e] = U[src][64-block] (bias, w=1) + sum_k hid[e,k]*U[src][k-block]
//   Predicated LDG.128 skips relu-zeroed k (uniform predicate per warp).
// ===========================================================================
#define MEB 8   // edges per block (8 warps, 256 threads)
__global__ __launch_bounds__(256) void msg_kernel(const int* __restrict__ edge_index) {
    __shared__ float hid_s[MEB][MH];
    __shared__ int s_src[MEB], s_tgt[MEB];
    int tid = threadIdx.x;
    int e0 = blockIdx.x * MEB;
    if (tid < MEB) {
        s_src[tid] = edge_index[e0 + tid];
        s_tgt[tid] = edge_index[EE + e0 + tid];
    }
    for (int idx = tid; idx < MEB * MH; idx += 256)
        hid_s[idx >> 6][idx & 63] = g_hid[e0 * MH + idx];
    __syncthreads();

    int we = tid >> 5, lane = tid & 31;
    const float4* Ur = reinterpret_cast<const float4*>(
        g_U + (size_t)s_src[we] * KC2) + lane;

    float4 a0 = Ur[MH * 32];                // bias block, weight 1
    float4 a1 = make_float4(0.f, 0.f, 0.f, 0.f);
    #pragma unroll 8
    for (int k = 0; k < MH; k += 2) {
        float w0 = hid_s[we][k], w1 = hid_s[we][k + 1];
        if (w0 != 0.f) {
            float4 v = Ur[k * 32];
            a0.x += w0 * v.x; a0.y += w0 * v.y; a0.z += w0 * v.z; a0.w += w0 * v.w;
        }
        if (w1 != 0.f) {
            float4 v = Ur[(k + 1) * 32];
            a1.x += w1 * v.x; a1.y += w1 * v.y; a1.z += w1 * v.z; a1.w += w1 * v.w;
        }
    }
    float* mdst = g_m + s_tgt[we] * HD + lane * 4;
    atomicAdd(mdst + 0, a0.x + a1.x);
    atomicAdd(mdst + 1, a0.y + a1.y);
    atomicAdd(mdst + 2, a0.z + a1.z);
    atomicAdd(mdst + 3, a0.w + a1.w);
}

// ===========================================================================
// gru_elem: fused gate nonlinearity + blend (coalesced, memory-bound)
// ===========================================================================
__global__ void gru_elem(const float* __restrict__ hin,
                         const float* __restrict__ b_ih, const float* __restrict__ b_hh,
                         float* __restrict__ out) {
    int idx = blockIdx.x * blockDim.x + threadIdx.x;    // n*128 + i
    int n = idx >> 7, i = idx & 127;
    const float* gi = g_gi + n * G3;
    const float* gh = g_gh + n * G3;
    float r = 1.0f / (1.0f + expf(-(gi[i] + b_ih[i] + gh[i] + b_hh[i])));
    float z = 1.0f / (1.0f + expf(-(gi[HD + i] + b_ih[HD + i] + gh[HD + i] + b_hh[HD + i])));
    float ng = tanhf(gi[2 * HD + i] + b_ih[2 * HD + i]
                     + r * (gh[2 * HD + i] + b_hh[2 * HD + i]));
    float hv = hin[idx];
    out[idx] = (1.0f - z) * ng + z * hv;
}

// ===========================================================================
// metadata order: h, edge_index, edge_features, W1, b1, W2, b2,
//                 W_ih, W_hh, b_ih, b_hh ; output float32 [N, H]
// ===========================================================================
extern "C" void kernel_launch(void* const* d_in, const int* in_sizes, int n_in,
                              void* d_out, int out_size) {
    const float* h_ptr      = (const float*)d_in[0];
    const int*   edge_index = (const int*)  d_in[1];
    const float* ef         = (const float*)d_in[2];
    const float* W1         = (const float*)d_in[3];
    const float* b1         = (const float*)d_in[4];
    const float* W2         = (const float*)d_in[5];
    const float* b2         = (const float*)d_in[6];
    const float* W_ih       = (const float*)d_in[7];
    const float* W_hh       = (const float*)d_in[8];
    const float* b_ih       = (const float*)d_in[9];
    const float* b_hh       = (const float*)d_in[10];
    float* out = (float*)d_out;

    cudaFuncSetAttribute(u_mma_kernel, cudaFuncAttributeMaxDynamicSharedMemorySize,
                         U_SMEM_BYTES);
    cudaFuncSetAttribute(gate_mma_kernel, cudaFuncAttributeMaxDynamicSharedMemorySize,
                         U_SMEM_BYTES);

    hid_kernel<<<(EE * MH) / 256, 256>>>(ef, W1, b1);
    u_mma_kernel<<<dim3(NN / 128, KC2 / 128), 512, U_SMEM_BYTES>>>(h_ptr, W2, b2);
    msg_kernel<<<EE / MEB, 256>>>(edge_index);
    gate_mma_kernel<<<dim3(NN / 128, 3, 2), 512, U_SMEM_BYTES>>>(h_ptr, W_ih, W_hh);
    gru_elem<<<(NN * HD) / 256, 256>>>(h_ptr, b_ih, b_hh, out);
}